// round 4
// baseline (speedup 1.0000x reference)
#include <cuda_runtime.h>
#include <math.h>

#define HID 1024
#define IN_SIZE 228
#define COND_SIZE 100
#define N_COND 40
#define VOCAB 32000
#define NSTEPS 512
#define FEAT 1252           // HID + IN_SIZE
#define SCAN_CTAS 128

// ---------------- scratch (device globals; no allocation allowed) ------------
__device__ float g_de[IN_SIZE];
__device__ float g_h0[HID];
__device__ float g_gi[2 * 3 * HID];      // [variant][3H], b_ih folded in; b_hh folded for r,u rows
__device__ float g_outde[VOCAB];         // de-part + out_b
__device__ float g_hs[NSTEPS * HID];     // all hidden states (GEMM A matrix)
__device__ unsigned int g_arrive[SCAN_CTAS * 32]; // per-CTA arrival words, 128B apart
__device__ unsigned int g_flag;          // single release word (light polling)

// ---------------- f32x2 helpers (packed fp32 pipe) ---------------------------
__device__ __forceinline__ unsigned long long pk2(float lo, float hi) {
    unsigned long long r;
    asm("mov.b64 %0, {%1,%2};" : "=l"(r) : "f"(lo), "f"(hi));
    return r;
}
__device__ __forceinline__ unsigned long long fma2(unsigned long long a,
                                                   unsigned long long b,
                                                   unsigned long long c) {
    unsigned long long d;
    asm("fma.rn.f32x2 %0, %1, %2, %3;" : "=l"(d) : "l"(a), "l"(b), "l"(c));
    return d;
}
__device__ __forceinline__ float2 upk2(unsigned long long v) {
    float2 f;
    asm("mov.b64 {%0,%1}, %2;" : "=f"(f.x), "=f"(f.y) : "l"(v));
    return f;
}
__device__ __forceinline__ void st_release_u32(unsigned int* p, unsigned int v) {
    asm volatile("st.release.gpu.global.u32 [%0], %1;" :: "l"(p), "r"(v) : "memory");
}
__device__ __forceinline__ unsigned int ld_acquire_u32(const unsigned int* p) {
    unsigned int v;
    asm volatile("ld.acquire.gpu.global.u32 %0, [%1];" : "=r"(v) : "l"(p) : "memory");
    return v;
}

// ---------------- prep: de, h0, barrier reset --------------------------------
__global__ void prep_kernel(const float* __restrict__ z,
                            const float* __restrict__ cond,
                            const float* __restrict__ i2h_W,
                            const float* __restrict__ i2h_b,
                            const float* __restrict__ c2h_W,
                            const float* __restrict__ c2h_b) {
    __shared__ float sde[IN_SIZE];
    int tid = threadIdx.x;
    if (tid < 128) sde[tid] = z[tid];
    if (tid < COND_SIZE) {
        float acc = c2h_b[tid];
#pragma unroll
        for (int k = 0; k < N_COND; k++) acc += cond[k] * c2h_W[tid * N_COND + k];
        sde[128 + tid] = acc;
    }
    if (tid == 0) g_flag = 0u;
    for (int i = tid; i < SCAN_CTAS * 32; i += blockDim.x) g_arrive[i] = 0u;
    __syncthreads();
    if (tid < IN_SIZE) g_de[tid] = sde[tid];
    for (int r = tid; r < HID; r += blockDim.x) {
        float acc = i2h_b[r];
        const float* w = i2h_W + (size_t)r * IN_SIZE;
#pragma unroll 4
        for (int k = 0; k < IN_SIZE; k++) acc += sde[k] * w[k];
        g_h0[r] = acc;
    }
}

// ---------------- gi: the 2 distinct input-gate rows -------------------------
__global__ void gi_kernel(const float* __restrict__ embed_W,
                          const float* __restrict__ W_ih,
                          const float* __restrict__ b_ih,
                          const float* __restrict__ b_hh) {
    __shared__ float xs[2][FEAT];
    int tid = threadIdx.x;
    for (int i = tid; i < HID; i += blockDim.x) {
        xs[0][i] = fmaxf(embed_W[1 * HID + i], 0.f);  // SOS = 1
        xs[1][i] = fmaxf(embed_W[2 * HID + i], 0.f);  // UNK = 2
    }
    for (int i = tid; i < IN_SIZE; i += blockDim.x) {
        float d = g_de[i];
        xs[0][HID + i] = d;
        xs[1][HID + i] = d;
    }
    __syncthreads();
    int lane = tid & 31;
    int warp = (blockIdx.x * blockDim.x + tid) >> 5;
    int nwarp = (gridDim.x * blockDim.x) >> 5;
    for (int task = warp; task < 2 * 3 * HID; task += nwarp) {
        int v = task >= 3 * HID;
        int row = task - v * 3 * HID;
        const float* w = W_ih + (size_t)row * FEAT;
        const float* x = xs[v];
        float acc = 0.f;
        for (int k = lane; k < FEAT; k += 32) acc += w[k] * x[k];
#pragma unroll
        for (int o = 16; o > 0; o >>= 1) acc += __shfl_xor_sync(0xffffffffu, acc, o);
        if (lane == 0) {
            float val = acc + b_ih[row];
            if (row < 2 * HID) val += b_hh[row];  // fold b_hh for r,u gates
            g_gi[task] = val;
        }
    }
}

// ---------------- outde: broadcast term of the output ------------------------
__global__ void outde_kernel(const float* __restrict__ out_W,
                             const float* __restrict__ out_b) {
    __shared__ float sde[IN_SIZE];
    int tid = threadIdx.x;
    if (tid < IN_SIZE) sde[tid] = g_de[tid];
    __syncthreads();
    int v = blockIdx.x * blockDim.x + tid;
    if (v < VOCAB) {
        const float* w = out_W + (size_t)v * FEAT + HID;
        float acc = out_b[v];
#pragma unroll 4
        for (int k = 0; k < IN_SIZE; k++) acc += sde[k] * w[k];
        g_outde[v] = acc;
    }
}

// ---------------- scan: persistent GRU, weights in registers -----------------
// 128 CTAs x 288 threads. Warps 0-7 compute (warp w owns hidden index
// j = bid*8 + w; W_hh rows {j, H+j, 2H+j} in 48 packed f32x2 regs each lane).
// Warp 8 of CTA 0 = barrier master. NO atomics, NO shared-address poll storms:
//   arrive:  1 release-store per CTA to a private 128B-spread word
//   detect:  master warp reads 128 words (4/lane, distinct lines)
//   release: master release-stores step# to ONE flag word
//   wait:    1 thread per CTA polls the flag (127 light pollers)
__global__ void __launch_bounds__(288) scan_kernel(const float* __restrict__ W_hh,
                                                   const float* __restrict__ b_hh) {
    __shared__ float sh[HID];
    int tid = threadIdx.x;
    int lane = tid & 31;
    int w = tid >> 5;
    int bid = blockIdx.x;
    bool comp = (w < 8);
    int j = bid * 8 + (comp ? w : 0);

    const float* Wr = W_hh + (size_t)j * HID;
    const float* Wu = W_hh + (size_t)(HID + j) * HID;
    const float* Wn = W_hh + (size_t)(2 * HID + j) * HID;

    unsigned long long wr2[16], wu2[16], wn2[16];
    if (comp) {
#pragma unroll
        for (int k = 0; k < 16; k++) {
            float2 a = *(const float2*)(Wr + 64 * k + 2 * lane); wr2[k] = pk2(a.x, a.y);
            float2 b = *(const float2*)(Wu + 64 * k + 2 * lane); wu2[k] = pk2(b.x, b.y);
            float2 c = *(const float2*)(Wn + 64 * k + 2 * lane); wn2[k] = pk2(c.x, c.y);
        }
    }
    float gi_r0 = g_gi[j],           gi_u0 = g_gi[HID + j],     gi_n0 = g_gi[2 * HID + j];
    float gi_r1 = g_gi[3 * HID + j], gi_u1 = g_gi[4 * HID + j], gi_n1 = g_gi[5 * HID + j];
    float bhn = b_hh[2 * HID + j];

    for (int t = 0; t < NSTEPS; t++) {
        // stage current h into smem (L2-coherent load; other SMs wrote it)
        if (comp) {
            const float4* src = (const float4*)((t == 0) ? g_h0 : (g_hs + (size_t)(t - 1) * HID));
            ((float4*)sh)[tid] = __ldcg(src + tid);
        }
        __syncthreads();

        if (comp) {
            unsigned long long ar2 = 0ull, au2 = 0ull, an2 = 0ull;
#pragma unroll
            for (int k = 0; k < 16; k++) {
                float2 h2 = *(const float2*)&sh[64 * k + 2 * lane];
                unsigned long long hp = pk2(h2.x, h2.y);
                ar2 = fma2(wr2[k], hp, ar2);
                au2 = fma2(wu2[k], hp, au2);
                an2 = fma2(wn2[k], hp, an2);
            }
            float2 fr = upk2(ar2), fu = upk2(au2), fn = upk2(an2);
            float ar = fr.x + fr.y, au = fu.x + fu.y, an = fn.x + fn.y;
#pragma unroll
            for (int o = 16; o > 0; o >>= 1) {
                ar += __shfl_xor_sync(0xffffffffu, ar, o);
                au += __shfl_xor_sync(0xffffffffu, au, o);
                an += __shfl_xor_sync(0xffffffffu, an, o);
            }
            float gr = (t == 0) ? gi_r0 : gi_r1;
            float gu = (t == 0) ? gi_u0 : gi_u1;
            float gn = (t == 0) ? gi_n0 : gi_n1;
            float r = 1.f / (1.f + __expf(-(gr + ar)));
            float u = 1.f / (1.f + __expf(-(gu + au)));
            float narg = gn + r * (an + bhn);
            float n = 1.f - 2.f / (__expf(2.f * narg) + 1.f);   // tanh
            float hnew = (1.f - u) * n + u * sh[j];
            if (lane == 0) __stcg(g_hs + (size_t)t * HID + j, hnew);
        }
        __syncthreads();   // all 8 compute warps' h-stores issued

        unsigned tgt = (unsigned)(t + 1);
        // arrive: one release-store per CTA (private word, 128B apart)
        if (w == 0 && lane == 0) st_release_u32(&g_arrive[bid * 32], tgt);
        // master: detect all 128 arrivals, then single-flag release
        if (w == 8 && bid == 0) {
            for (;;) {
                unsigned a = ld_acquire_u32(&g_arrive[lane * 32]);
                unsigned b = ld_acquire_u32(&g_arrive[(lane + 32) * 32]);
                unsigned c = ld_acquire_u32(&g_arrive[(lane + 64) * 32]);
                unsigned d = ld_acquire_u32(&g_arrive[(lane + 96) * 32]);
                unsigned m = (a >= tgt) & (b >= tgt) & (c >= tgt) & (d >= tgt);
                if (__all_sync(0xffffffffu, m)) break;
            }
            if (lane == 0) st_release_u32(&g_flag, tgt);
        }
        // wait: single light poller per CTA on one shared word
        if (w == 0 && lane == 0) {
            while (ld_acquire_u32(&g_flag) < tgt) {}
        }
        __syncthreads();   // release all warps into the next step
    }
}

// ---------------- output GEMM: C[512,32000] = hs @ W[:, :1024]^T + outde -----
// BM=128, BN=128, BK=16, 256 threads, 8x8 per thread via f32x2 (32 packed acc).
#define BM 128
#define BN 128
#define BK 16
#define SPAD 4
__global__ void __launch_bounds__(256) gemm_kernel(const float* __restrict__ BW,
                                                   float* __restrict__ out) {
    __shared__ float As[BK][BM + SPAD];
    __shared__ float Bs[BK][BN + SPAD];
    int tid = threadIdx.x;
    int tx = tid & 15, ty = tid >> 4;
    int tn = blockIdx.x * BN;
    int tm = blockIdx.y * BM;

    unsigned long long acc[8][4];
#pragma unroll
    for (int i = 0; i < 8; i++)
#pragma unroll
        for (int p = 0; p < 4; p++) acc[i][p] = 0ull;

    for (int k0 = 0; k0 < HID; k0 += BK) {
#pragma unroll
        for (int rep = 0; rep < 2; rep++) {
            int idx = tid + rep * 256;
            int row = idx >> 2, kq = idx & 3;
            float4 va = *(const float4*)(g_hs + (size_t)(tm + row) * HID + k0 + kq * 4);
            As[kq * 4 + 0][row] = va.x; As[kq * 4 + 1][row] = va.y;
            As[kq * 4 + 2][row] = va.z; As[kq * 4 + 3][row] = va.w;
            float4 vb = *(const float4*)(BW + (size_t)(tn + row) * FEAT + k0 + kq * 4);
            Bs[kq * 4 + 0][row] = vb.x; Bs[kq * 4 + 1][row] = vb.y;
            Bs[kq * 4 + 2][row] = vb.z; Bs[kq * 4 + 3][row] = vb.w;
        }
        __syncthreads();
#pragma unroll
        for (int k = 0; k < BK; k++) {
            float4 a0 = *(const float4*)&As[k][ty * 4];
            float4 a1 = *(const float4*)&As[k][64 + ty * 4];
            float4 b0 = *(const float4*)&Bs[k][tx * 4];
            float4 b1 = *(const float4*)&Bs[k][64 + tx * 4];
            unsigned long long bp[4] = { pk2(b0.x, b0.y), pk2(b0.z, b0.w),
                                         pk2(b1.x, b1.y), pk2(b1.z, b1.w) };
            float am[8] = { a0.x, a0.y, a0.z, a0.w, a1.x, a1.y, a1.z, a1.w };
#pragma unroll
            for (int mi = 0; mi < 8; mi++) {
                unsigned long long ap = pk2(am[mi], am[mi]);
#pragma unroll
                for (int p = 0; p < 4; p++) acc[mi][p] = fma2(ap, bp[p], acc[mi][p]);
            }
        }
        __syncthreads();
    }

    float4 od0 = *(const float4*)(g_outde + tn + tx * 4);
    float4 od1 = *(const float4*)(g_outde + tn + 64 + tx * 4);
#pragma unroll
    for (int mi = 0; mi < 8; mi++) {
        int m = tm + ((mi < 4) ? (ty * 4 + mi) : (64 + ty * 4 + (mi - 4)));
        float2 c0 = upk2(acc[mi][0]), c1 = upk2(acc[mi][1]);
        float2 c2 = upk2(acc[mi][2]), c3 = upk2(acc[mi][3]);
        float4 o0 = { c0.x + od0.x, c0.y + od0.y, c1.x + od0.z, c1.y + od0.w };
        float4 o1 = { c2.x + od1.x, c2.y + od1.y, c3.x + od1.z, c3.y + od1.w };
        *(float4*)(out + (size_t)m * VOCAB + tn + tx * 4) = o0;
        *(float4*)(out + (size_t)m * VOCAB + tn + 64 + tx * 4) = o1;
    }
}

// ---------------- entry ------------------------------------------------------
extern "C" void kernel_launch(void* const* d_in, const int* in_sizes, int n_in,
                              void* d_out, int out_size) {
    const float* z      = (const float*)d_in[0];
    const float* cond   = (const float*)d_in[1];
    // d_in[2] = inputs (unused: word_dropout=1.0), d_in[3] = temperature (unused)
    const float* embedW = (const float*)d_in[4];
    const float* W_ih   = (const float*)d_in[5];
    const float* W_hh   = (const float*)d_in[6];
    const float* b_ih   = (const float*)d_in[7];
    const float* b_hh   = (const float*)d_in[8];
    const float* i2h_W  = (const float*)d_in[9];
    const float* i2h_b  = (const float*)d_in[10];
    const float* c2h_W  = (const float*)d_in[11];
    const float* c2h_b  = (const float*)d_in[12];
    const float* out_W  = (const float*)d_in[13];
    const float* out_b  = (const float*)d_in[14];
    float* out = (float*)d_out;

    prep_kernel<<<1, 256>>>(z, cond, i2h_W, i2h_b, c2h_W, c2h_b);
    gi_kernel<<<96, 256>>>(embedW, W_ih, b_ih, b_hh);
    outde_kernel<<<(VOCAB + 255) / 256, 256>>>(out_W, out_b);
    scan_kernel<<<SCAN_CTAS, 288>>>(W_hh, b_hh);
    gemm_kernel<<<dim3(VOCAB / BN, NSTEPS / BM), 256>>>(out_W, out);
}

// round 5
// speedup vs baseline: 1.6284x; 1.6284x over previous
#include <cuda_runtime.h>
#include <math.h>

#define HID 1024
#define IN_SIZE 228
#define COND_SIZE 100
#define N_COND 40
#define VOCAB 32000
#define NSTEPS 512
#define FEAT 1252           // HID + IN_SIZE
#define SCAN_CTAS 128
#define NGRP 16             // 16 groups x 8 CTAs

// ---------------- scratch (device globals; no allocation allowed) ------------
__device__ float g_de[IN_SIZE];
__device__ float g_h0[HID];
__device__ float g_gi[2 * 3 * HID];      // [variant][3H], b_ih folded in; b_hh folded for r,u rows
__device__ float g_outde[VOCAB];         // de-part + out_b
__device__ float g_hs[NSTEPS * HID];     // all hidden states (GEMM A matrix)
__device__ unsigned int g_cnt1[NGRP * 32]; // group counters, 128B apart
__device__ unsigned int g_cnt2;            // root counter
__device__ volatile unsigned int g_flag;   // single release flag (light polling, R1-proven)

// ---------------- f32x2 helpers (packed fp32 pipe) ---------------------------
__device__ __forceinline__ unsigned long long pk2(float lo, float hi) {
    unsigned long long r;
    asm("mov.b64 %0, {%1,%2};" : "=l"(r) : "f"(lo), "f"(hi));
    return r;
}
__device__ __forceinline__ unsigned long long fma2(unsigned long long a,
                                                   unsigned long long b,
                                                   unsigned long long c) {
    unsigned long long d;
    asm("fma.rn.f32x2 %0, %1, %2, %3;" : "=l"(d) : "l"(a), "l"(b), "l"(c));
    return d;
}
__device__ __forceinline__ float2 upk2(unsigned long long v) {
    float2 f;
    asm("mov.b64 {%0,%1}, %2;" : "=f"(f.x), "=f"(f.y) : "l"(v));
    return f;
}

// ---------------- prep: de, h0, barrier reset --------------------------------
__global__ void prep_kernel(const float* __restrict__ z,
                            const float* __restrict__ cond,
                            const float* __restrict__ i2h_W,
                            const float* __restrict__ i2h_b,
                            const float* __restrict__ c2h_W,
                            const float* __restrict__ c2h_b) {
    __shared__ float sde[IN_SIZE];
    int tid = threadIdx.x;
    if (tid < 128) sde[tid] = z[tid];
    if (tid < COND_SIZE) {
        float acc = c2h_b[tid];
#pragma unroll
        for (int k = 0; k < N_COND; k++) acc += cond[k] * c2h_W[tid * N_COND + k];
        sde[128 + tid] = acc;
    }
    if (tid == 0) { g_cnt2 = 0u; g_flag = 0u; }
    for (int i = tid; i < NGRP * 32; i += blockDim.x) g_cnt1[i] = 0u;
    __syncthreads();
    if (tid < IN_SIZE) g_de[tid] = sde[tid];
    for (int r = tid; r < HID; r += blockDim.x) {
        float acc = i2h_b[r];
        const float* w = i2h_W + (size_t)r * IN_SIZE;
#pragma unroll 4
        for (int k = 0; k < IN_SIZE; k++) acc += sde[k] * w[k];
        g_h0[r] = acc;
    }
}

// ---------------- gi: the 2 distinct input-gate rows -------------------------
__global__ void gi_kernel(const float* __restrict__ embed_W,
                          const float* __restrict__ W_ih,
                          const float* __restrict__ b_ih,
                          const float* __restrict__ b_hh) {
    __shared__ float xs[2][FEAT];
    int tid = threadIdx.x;
    for (int i = tid; i < HID; i += blockDim.x) {
        xs[0][i] = fmaxf(embed_W[1 * HID + i], 0.f);  // SOS = 1
        xs[1][i] = fmaxf(embed_W[2 * HID + i], 0.f);  // UNK = 2
    }
    for (int i = tid; i < IN_SIZE; i += blockDim.x) {
        float d = g_de[i];
        xs[0][HID + i] = d;
        xs[1][HID + i] = d;
    }
    __syncthreads();
    int lane = tid & 31;
    int warp = (blockIdx.x * blockDim.x + tid) >> 5;
    int nwarp = (gridDim.x * blockDim.x) >> 5;
    for (int task = warp; task < 2 * 3 * HID; task += nwarp) {
        int v = task >= 3 * HID;
        int row = task - v * 3 * HID;
        const float* w = W_ih + (size_t)row * FEAT;
        const float* x = xs[v];
        float acc = 0.f;
        for (int k = lane; k < FEAT; k += 32) acc += w[k] * x[k];
#pragma unroll
        for (int o = 16; o > 0; o >>= 1) acc += __shfl_xor_sync(0xffffffffu, acc, o);
        if (lane == 0) {
            float val = acc + b_ih[row];
            if (row < 2 * HID) val += b_hh[row];  // fold b_hh for r,u gates
            g_gi[task] = val;
        }
    }
}

// ---------------- outde: broadcast term of the output ------------------------
__global__ void outde_kernel(const float* __restrict__ out_W,
                             const float* __restrict__ out_b) {
    __shared__ float sde[IN_SIZE];
    int tid = threadIdx.x;
    if (tid < IN_SIZE) sde[tid] = g_de[tid];
    __syncthreads();
    int v = blockIdx.x * blockDim.x + tid;
    if (v < VOCAB) {
        const float* w = out_W + (size_t)v * FEAT + HID;
        float acc = out_b[v];
#pragma unroll 4
        for (int k = 0; k < IN_SIZE; k++) acc += sde[k] * w[k];
        g_outde[v] = acc;
    }
}

// ---------------- scan: persistent GRU, weights in registers -----------------
// 128 CTAs x 256 threads (8 warps). Warp w of CTA c owns hidden index
// j = c*8 + w and W_hh rows {j, H+j, 2H+j}, stored as 48 packed f32x2 regs.
// Barrier = R1's proven structure (threadfence + atomic arrive + ONE volatile
// flag + single-word spin) with the flat 128-way atomic replaced by a 2-level
// tree: 16 group counters (8 CTAs each, 128B apart) -> 1 root counter.
// No acquire-load polling anywhere (chained acquires serialize; measured R2/R4).
__global__ void __launch_bounds__(256) scan_kernel(const float* __restrict__ W_hh,
                                                   const float* __restrict__ b_hh) {
    __shared__ float sh[HID];
    int tid = threadIdx.x;
    int lane = tid & 31;
    int w = tid >> 5;
    int bid = blockIdx.x;
    int j = bid * 8 + w;

    const float* Wr = W_hh + (size_t)j * HID;
    const float* Wu = W_hh + (size_t)(HID + j) * HID;
    const float* Wn = W_hh + (size_t)(2 * HID + j) * HID;

    unsigned long long wr2[16], wu2[16], wn2[16];
#pragma unroll
    for (int k = 0; k < 16; k++) {
        float2 a = *(const float2*)(Wr + 64 * k + 2 * lane); wr2[k] = pk2(a.x, a.y);
        float2 b = *(const float2*)(Wu + 64 * k + 2 * lane); wu2[k] = pk2(b.x, b.y);
        float2 c = *(const float2*)(Wn + 64 * k + 2 * lane); wn2[k] = pk2(c.x, c.y);
    }
    float gi_r0 = g_gi[j],           gi_u0 = g_gi[HID + j],     gi_n0 = g_gi[2 * HID + j];
    float gi_r1 = g_gi[3 * HID + j], gi_u1 = g_gi[4 * HID + j], gi_n1 = g_gi[5 * HID + j];
    float bhn = b_hh[2 * HID + j];
    const int grp = bid >> 3;            // 16 groups of 8 consecutive CTAs

    for (int t = 0; t < NSTEPS; t++) {
        // stage current h into smem (L2-coherent load; other SMs wrote it)
        const float4* src = (const float4*)((t == 0) ? g_h0 : (g_hs + (size_t)(t - 1) * HID));
        ((float4*)sh)[tid] = __ldcg(src + tid);
        __syncthreads();

        unsigned long long ar2 = 0ull, au2 = 0ull, an2 = 0ull;
#pragma unroll
        for (int k = 0; k < 16; k++) {
            float2 h2 = *(const float2*)&sh[64 * k + 2 * lane];
            unsigned long long hp = pk2(h2.x, h2.y);
            ar2 = fma2(wr2[k], hp, ar2);
            au2 = fma2(wu2[k], hp, au2);
            an2 = fma2(wn2[k], hp, an2);
        }
        float2 fr = upk2(ar2), fu = upk2(au2), fn = upk2(an2);
        float ar = fr.x + fr.y, au = fu.x + fu.y, an = fn.x + fn.y;
#pragma unroll
        for (int o = 16; o > 0; o >>= 1) {
            ar += __shfl_xor_sync(0xffffffffu, ar, o);
            au += __shfl_xor_sync(0xffffffffu, au, o);
            an += __shfl_xor_sync(0xffffffffu, an, o);
        }
        float gr = (t == 0) ? gi_r0 : gi_r1;
        float gu = (t == 0) ? gi_u0 : gi_u1;
        float gn = (t == 0) ? gi_n0 : gi_n1;
        float r = 1.f / (1.f + __expf(-(gr + ar)));
        float u = 1.f / (1.f + __expf(-(gu + au)));
        float narg = gn + r * (an + bhn);
        float n = 1.f - 2.f / (__expf(2.f * narg) + 1.f);   // tanh
        float hnew = (1.f - u) * n + u * sh[j];
        if (lane == 0) __stcg(g_hs + (size_t)t * HID + j, hnew);

        __threadfence();
        __syncthreads();
        if (tid == 0) {
            unsigned tgt = (unsigned)(t + 1);
            unsigned old = atomicAdd(&g_cnt1[grp * 32], 1u);
            if (old == 8u * tgt - 1u) {                 // last of this group
                unsigned o2 = atomicAdd(&g_cnt2, 1u);
                if (o2 == (unsigned)NGRP * tgt - 1u) {  // last group overall
                    __threadfence();
                    g_flag = tgt;                       // release
                }
            }
            while (g_flag < tgt) {}                     // single-word spin (R1-proven)
            __threadfence();
        }
        __syncthreads();
    }
}

// ---------------- output GEMM: C[512,32000] = hs @ W[:, :1024]^T + outde -----
// BM=128, BN=128, BK=16, 256 threads, 8x8 per thread via f32x2 (32 packed acc).
#define BM 128
#define BN 128
#define BK 16
#define SPAD 4
__global__ void __launch_bounds__(256) gemm_kernel(const float* __restrict__ BW,
                                                   float* __restrict__ out) {
    __shared__ float As[BK][BM + SPAD];
    __shared__ float Bs[BK][BN + SPAD];
    int tid = threadIdx.x;
    int tx = tid & 15, ty = tid >> 4;
    int tn = blockIdx.x * BN;
    int tm = blockIdx.y * BM;

    unsigned long long acc[8][4];
#pragma unroll
    for (int i = 0; i < 8; i++)
#pragma unroll
        for (int p = 0; p < 4; p++) acc[i][p] = 0ull;

    for (int k0 = 0; k0 < HID; k0 += BK) {
#pragma unroll
        for (int rep = 0; rep < 2; rep++) {
            int idx = tid + rep * 256;
            int row = idx >> 2, kq = idx & 3;
            float4 va = *(const float4*)(g_hs + (size_t)(tm + row) * HID + k0 + kq * 4);
            As[kq * 4 + 0][row] = va.x; As[kq * 4 + 1][row] = va.y;
            As[kq * 4 + 2][row] = va.z; As[kq * 4 + 3][row] = va.w;
            float4 vb = *(const float4*)(BW + (size_t)(tn + row) * FEAT + k0 + kq * 4);
            Bs[kq * 4 + 0][row] = vb.x; Bs[kq * 4 + 1][row] = vb.y;
            Bs[kq * 4 + 2][row] = vb.z; Bs[kq * 4 + 3][row] = vb.w;
        }
        __syncthreads();
#pragma unroll
        for (int k = 0; k < BK; k++) {
            float4 a0 = *(const float4*)&As[k][ty * 4];
            float4 a1 = *(const float4*)&As[k][64 + ty * 4];
            float4 b0 = *(const float4*)&Bs[k][tx * 4];
            float4 b1 = *(const float4*)&Bs[k][64 + tx * 4];
            unsigned long long bp[4] = { pk2(b0.x, b0.y), pk2(b0.z, b0.w),
                                         pk2(b1.x, b1.y), pk2(b1.z, b1.w) };
            float am[8] = { a0.x, a0.y, a0.z, a0.w, a1.x, a1.y, a1.z, a1.w };
#pragma unroll
            for (int mi = 0; mi < 8; mi++) {
                unsigned long long ap = pk2(am[mi], am[mi]);
#pragma unroll
                for (int p = 0; p < 4; p++) acc[mi][p] = fma2(ap, bp[p], acc[mi][p]);
            }
        }
        __syncthreads();
    }

    float4 od0 = *(const float4*)(g_outde + tn + tx * 4);
    float4 od1 = *(const float4*)(g_outde + tn + 64 + tx * 4);
#pragma unroll
    for (int mi = 0; mi < 8; mi++) {
        int m = tm + ((mi < 4) ? (ty * 4 + mi) : (64 + ty * 4 + (mi - 4)));
        float2 c0 = upk2(acc[mi][0]), c1 = upk2(acc[mi][1]);
        float2 c2 = upk2(acc[mi][2]), c3 = upk2(acc[mi][3]);
        float4 o0 = { c0.x + od0.x, c0.y + od0.y, c1.x + od0.z, c1.y + od0.w };
        float4 o1 = { c2.x + od1.x, c2.y + od1.y, c3.x + od1.z, c3.y + od1.w };
        *(float4*)(out + (size_t)m * VOCAB + tn + tx * 4) = o0;
        *(float4*)(out + (size_t)m * VOCAB + tn + 64 + tx * 4) = o1;
    }
}

// ---------------- entry ------------------------------------------------------
extern "C" void kernel_launch(void* const* d_in, const int* in_sizes, int n_in,
                              void* d_out, int out_size) {
    const float* z      = (const float*)d_in[0];
    const float* cond   = (const float*)d_in[1];
    // d_in[2] = inputs (unused: word_dropout=1.0), d_in[3] = temperature (unused)
    const float* embedW = (const float*)d_in[4];
    const float* W_ih   = (const float*)d_in[5];
    const float* W_hh   = (const float*)d_in[6];
    const float* b_ih   = (const float*)d_in[7];
    const float* b_hh   = (const float*)d_in[8];
    const float* i2h_W  = (const float*)d_in[9];
    const float* i2h_b  = (const float*)d_in[10];
    const float* c2h_W  = (const float*)d_in[11];
    const float* c2h_b  = (const float*)d_in[12];
    const float* out_W  = (const float*)d_in[13];
    const float* out_b  = (const float*)d_in[14];
    float* out = (float*)d_out;

    prep_kernel<<<1, 256>>>(z, cond, i2h_W, i2h_b, c2h_W, c2h_b);
    gi_kernel<<<96, 256>>>(embedW, W_ih, b_ih, b_hh);
    outde_kernel<<<(VOCAB + 255) / 256, 256>>>(out_W, out_b);
    scan_kernel<<<SCAN_CTAS, 256>>>(W_hh, b_hh);
    gemm_kernel<<<dim3(VOCAB / BN, NSTEPS / BM), 256>>>(out_W, out);
}

// round 8
// speedup vs baseline: 2.1214x; 1.3028x over previous
#include <cuda_runtime.h>
#include <cuda_bf16.h>
#include <math.h>

#define HID 1024
#define IN_SIZE 228
#define COND_SIZE 100
#define N_COND 40
#define VOCAB 32000
#define NSTEPS 512
#define FEAT 1252           // HID + IN_SIZE
#define SCAN_CTAS 128

// ---------------- scratch (device globals; no allocation allowed) ------------
__device__ float g_de[IN_SIZE];
__device__ float g_h0[HID];
__device__ float g_gi[2 * 3 * HID];
__device__ float g_outde[VOCAB];         // de-part + out_b
__device__ float g_hs[NSTEPS * HID];     // hidden states (GEMM A, fp32 master)
__device__ unsigned int g_cnt;           // R1 barrier: monotonic counter
__device__ volatile unsigned int g_flag; // R1 barrier: monotonic release flag
// split-bf16 operands for the tensor-core GEMM
__device__ __nv_bfloat16 g_ahi[NSTEPS * HID];
__device__ __nv_bfloat16 g_alo[NSTEPS * HID];
__device__ __nv_bfloat16 g_whi[(size_t)VOCAB * HID];
__device__ __nv_bfloat16 g_wlo[(size_t)VOCAB * HID];

// ---------------- f32x2 helpers ----------------------------------------------
__device__ __forceinline__ unsigned long long pk2(float lo, float hi) {
    unsigned long long r;
    asm("mov.b64 %0, {%1,%2};" : "=l"(r) : "f"(lo), "f"(hi));
    return r;
}
__device__ __forceinline__ unsigned long long fma2(unsigned long long a,
                                                   unsigned long long b,
                                                   unsigned long long c) {
    unsigned long long d;
    asm("fma.rn.f32x2 %0, %1, %2, %3;" : "=l"(d) : "l"(a), "l"(b), "l"(c));
    return d;
}
__device__ __forceinline__ float2 upk2(unsigned long long v) {
    float2 f;
    asm("mov.b64 {%0,%1}, %2;" : "=f"(f.x), "=f"(f.y) : "l"(v));
    return f;
}

// ---------------- prep: de, h0, barrier reset --------------------------------
__global__ void prep_kernel(const float* __restrict__ z,
                            const float* __restrict__ cond,
                            const float* __restrict__ i2h_W,
                            const float* __restrict__ i2h_b,
                            const float* __restrict__ c2h_W,
                            const float* __restrict__ c2h_b) {
    __shared__ float sde[IN_SIZE];
    int tid = threadIdx.x;
    if (tid < 128) sde[tid] = z[tid];
    if (tid < COND_SIZE) {
        float acc = c2h_b[tid];
#pragma unroll
        for (int k = 0; k < N_COND; k++) acc += cond[k] * c2h_W[tid * N_COND + k];
        sde[128 + tid] = acc;
    }
    if (tid == 0) { g_cnt = 0; g_flag = 0; }
    __syncthreads();
    if (tid < IN_SIZE) g_de[tid] = sde[tid];
    for (int r = tid; r < HID; r += blockDim.x) {
        float acc = i2h_b[r];
        const float* w = i2h_W + (size_t)r * IN_SIZE;
#pragma unroll 4
        for (int k = 0; k < IN_SIZE; k++) acc += sde[k] * w[k];
        g_h0[r] = acc;
    }
}

// ---------------- gi: the 2 distinct input-gate rows -------------------------
__global__ void gi_kernel(const float* __restrict__ embed_W,
                          const float* __restrict__ W_ih,
                          const float* __restrict__ b_ih,
                          const float* __restrict__ b_hh) {
    __shared__ float xs[2][FEAT];
    int tid = threadIdx.x;
    for (int i = tid; i < HID; i += blockDim.x) {
        xs[0][i] = fmaxf(embed_W[1 * HID + i], 0.f);  // SOS = 1
        xs[1][i] = fmaxf(embed_W[2 * HID + i], 0.f);  // UNK = 2
    }
    for (int i = tid; i < IN_SIZE; i += blockDim.x) {
        float d = g_de[i];
        xs[0][HID + i] = d;
        xs[1][HID + i] = d;
    }
    __syncthreads();
    int lane = tid & 31;
    int warp = (blockIdx.x * blockDim.x + tid) >> 5;
    int nwarp = (gridDim.x * blockDim.x) >> 5;
    for (int task = warp; task < 2 * 3 * HID; task += nwarp) {
        int v = task >= 3 * HID;
        int row = task - v * 3 * HID;
        const float* w = W_ih + (size_t)row * FEAT;
        const float* x = xs[v];
        float acc = 0.f;
        for (int k = lane; k < FEAT; k += 32) acc += w[k] * x[k];
#pragma unroll
        for (int o = 16; o > 0; o >>= 1) acc += __shfl_xor_sync(0xffffffffu, acc, o);
        if (lane == 0) {
            float val = acc + b_ih[row];
            if (row < 2 * HID) val += b_hh[row];
            g_gi[task] = val;
        }
    }
}

// ---------------- outde: broadcast term of the output ------------------------
__global__ void outde_kernel(const float* __restrict__ out_W,
                             const float* __restrict__ out_b) {
    __shared__ float sde[IN_SIZE];
    int tid = threadIdx.x;
    if (tid < IN_SIZE) sde[tid] = g_de[tid];
    __syncthreads();
    int v = blockIdx.x * blockDim.x + tid;
    if (v < VOCAB) {
        const float* w = out_W + (size_t)v * FEAT + HID;
        float acc = out_b[v];
#pragma unroll 4
        for (int k = 0; k < IN_SIZE; k++) acc += sde[k] * w[k];
        g_outde[v] = acc;
    }
}

// ---------------- W conversion: out_W[:, :1024] -> hi/lo bf16 ----------------
__global__ void wconv_kernel(const float* __restrict__ out_W) {
    size_t i8 = (size_t)blockIdx.x * blockDim.x + threadIdx.x;  // one 8-float group
    if (i8 >= (size_t)VOCAB * HID / 8) return;
    int r = (int)(i8 >> 7);          // vocab row
    int c8 = (int)(i8 & 127);        // group of 8 cols
    const float4* src = (const float4*)(out_W + (size_t)r * FEAT + c8 * 8);
    float4 v0 = src[0], v1 = src[1];
    float v[8] = { v0.x, v0.y, v0.z, v0.w, v1.x, v1.y, v1.z, v1.w };
    unsigned hu[4], lu[4];
#pragma unroll
    for (int p = 0; p < 4; p++) {
        __nv_bfloat16 h0 = __float2bfloat16(v[2 * p]);
        __nv_bfloat16 h1 = __float2bfloat16(v[2 * p + 1]);
        __nv_bfloat16 l0 = __float2bfloat16(v[2 * p] - __bfloat162float(h0));
        __nv_bfloat16 l1 = __float2bfloat16(v[2 * p + 1] - __bfloat162float(h1));
        hu[p] = (unsigned)__bfloat16_as_ushort(h0) | ((unsigned)__bfloat16_as_ushort(h1) << 16);
        lu[p] = (unsigned)__bfloat16_as_ushort(l0) | ((unsigned)__bfloat16_as_ushort(l1) << 16);
    }
    *(uint4*)(g_whi + i8 * 8) = make_uint4(hu[0], hu[1], hu[2], hu[3]);
    *(uint4*)(g_wlo + i8 * 8) = make_uint4(lu[0], lu[1], lu[2], lu[3]);
}

// ---------------- A conversion: g_hs -> hi/lo bf16 ---------------------------
__global__ void aconv_kernel() {
    size_t i8 = (size_t)blockIdx.x * blockDim.x + threadIdx.x;
    if (i8 >= (size_t)NSTEPS * HID / 8) return;
    const float4* src = (const float4*)(g_hs + i8 * 8);
    float4 v0 = src[0], v1 = src[1];
    float v[8] = { v0.x, v0.y, v0.z, v0.w, v1.x, v1.y, v1.z, v1.w };
    unsigned hu[4], lu[4];
#pragma unroll
    for (int p = 0; p < 4; p++) {
        __nv_bfloat16 h0 = __float2bfloat16(v[2 * p]);
        __nv_bfloat16 h1 = __float2bfloat16(v[2 * p + 1]);
        __nv_bfloat16 l0 = __float2bfloat16(v[2 * p] - __bfloat162float(h0));
        __nv_bfloat16 l1 = __float2bfloat16(v[2 * p + 1] - __bfloat162float(h1));
        hu[p] = (unsigned)__bfloat16_as_ushort(h0) | ((unsigned)__bfloat16_as_ushort(h1) << 16);
        lu[p] = (unsigned)__bfloat16_as_ushort(l0) | ((unsigned)__bfloat16_as_ushort(l1) << 16);
    }
    *(uint4*)(g_ahi + i8 * 8) = make_uint4(hu[0], hu[1], hu[2], hu[3]);
    *(uint4*)(g_alo + i8 * 8) = make_uint4(lu[0], lu[1], lu[2], lu[3]);
}

// ---------------- scan: R1-EXACT barrier (measured best: 2.35us/step) --------
__global__ void __launch_bounds__(256) scan_kernel(const float* __restrict__ W_hh,
                                                   const float* __restrict__ b_hh) {
    __shared__ float sh[HID];
    int tid = threadIdx.x;
    int lane = tid & 31;
    int w = tid >> 5;
    int j = blockIdx.x * 8 + w;

    const float* Wr = W_hh + (size_t)j * HID;
    const float* Wu = W_hh + (size_t)(HID + j) * HID;
    const float* Wn = W_hh + (size_t)(2 * HID + j) * HID;

    unsigned long long wr2[16], wu2[16], wn2[16];
#pragma unroll
    for (int k = 0; k < 16; k++) {
        float2 a = *(const float2*)(Wr + 64 * k + 2 * lane); wr2[k] = pk2(a.x, a.y);
        float2 b = *(const float2*)(Wu + 64 * k + 2 * lane); wu2[k] = pk2(b.x, b.y);
        float2 c = *(const float2*)(Wn + 64 * k + 2 * lane); wn2[k] = pk2(c.x, c.y);
    }
    float gi_r0 = g_gi[j],           gi_u0 = g_gi[HID + j],     gi_n0 = g_gi[2 * HID + j];
    float gi_r1 = g_gi[3 * HID + j], gi_u1 = g_gi[4 * HID + j], gi_n1 = g_gi[5 * HID + j];
    float bhn = b_hh[2 * HID + j];
    const unsigned nCTA = gridDim.x;

    for (int t = 0; t < NSTEPS; t++) {
        const float4* src = (const float4*)((t == 0) ? g_h0 : (g_hs + (size_t)(t - 1) * HID));
        ((float4*)sh)[tid] = __ldcg(src + tid);
        __syncthreads();

        unsigned long long ar2 = 0ull, au2 = 0ull, an2 = 0ull;
#pragma unroll
        for (int k = 0; k < 16; k++) {
            float2 h2 = *(const float2*)&sh[64 * k + 2 * lane];
            unsigned long long hp = pk2(h2.x, h2.y);
            ar2 = fma2(wr2[k], hp, ar2);
            au2 = fma2(wu2[k], hp, au2);
            an2 = fma2(wn2[k], hp, an2);
        }
        float2 fr = upk2(ar2), fu = upk2(au2), fn = upk2(an2);
        float ar = fr.x + fr.y, au = fu.x + fu.y, an = fn.x + fn.y;
#pragma unroll
        for (int o = 16; o > 0; o >>= 1) {
            ar += __shfl_xor_sync(0xffffffffu, ar, o);
            au += __shfl_xor_sync(0xffffffffu, au, o);
            an += __shfl_xor_sync(0xffffffffu, an, o);
        }
        if (lane == 0) {
            float gr = (t == 0) ? gi_r0 : gi_r1;
            float gu = (t == 0) ? gi_u0 : gi_u1;
            float gn = (t == 0) ? gi_n0 : gi_n1;
            float r = 1.f / (1.f + __expf(-(gr + ar)));
            float u = 1.f / (1.f + __expf(-(gu + au)));
            float narg = gn + r * (an + bhn);
            float n = 1.f - 2.f / (__expf(2.f * narg) + 1.f);
            float hnew = (1.f - u) * n + u * sh[j];
            __stcg(g_hs + (size_t)t * HID + j, hnew);
        }
        __threadfence();
        __syncthreads();
        if (tid == 0) {
            unsigned target = nCTA * (unsigned)(t + 1);
            unsigned old = atomicAdd(&g_cnt, 1u);
            if (old == target - 1u) {
                g_flag = (unsigned)(t + 1);           // release
            } else {
                while (g_flag < (unsigned)(t + 1)) {} // spin (measured benign)
            }
            __threadfence();
        }
        __syncthreads();
    }
}

// ---------------- tensor-core GEMM: split-bf16, mma.sync m16n8k16 ------------
// C[512,32000] = (Ahi+Alo)(Whi+Wlo)^T + outde, dropping lo*lo.
// CTA tile 128x128, K-tile 32; 8 warps as 2(M)x4(N), warp tile 64x32.
#define MMA_OP(d, a, b)                                                        \
    asm("mma.sync.aligned.m16n8k16.row.col.f32.bf16.bf16.f32 "                 \
        "{%0,%1,%2,%3}, {%4,%5,%6,%7}, {%8,%9}, {%0,%1,%2,%3};"                \
        : "+f"(d[0]), "+f"(d[1]), "+f"(d[2]), "+f"(d[3])                        \
        : "r"(a[0]), "r"(a[1]), "r"(a[2]), "r"(a[3]), "r"(b[0]), "r"(b[1]))

#define KPAD 40   // 32 + 8 halves: conflict-free frag loads

__global__ void __launch_bounds__(256) mma_gemm_kernel(float* __restrict__ out) {
    __shared__ __nv_bfloat16 As[2][128][KPAD];   // [hi/lo][m][k]
    __shared__ __nv_bfloat16 Bs[2][128][KPAD];   // [hi/lo][n][k]
    int tid = threadIdx.x;
    int lane = tid & 31, wid = tid >> 5;
    int wm = wid & 1, wn = wid >> 1;             // 2 x 4 warp grid
    int g = lane >> 2, tig = lane & 3;
    int tn = blockIdx.x * 128, tm = blockIdx.y * 128;

    float acc[4][4][4];
#pragma unroll
    for (int mi = 0; mi < 4; mi++)
#pragma unroll
        for (int ni = 0; ni < 4; ni++)
#pragma unroll
            for (int p = 0; p < 4; p++) acc[mi][ni][p] = 0.f;

    for (int k0 = 0; k0 < HID; k0 += 32) {
        __syncthreads();
        // load 4 tiles (A hi/lo, B hi/lo), each 128 rows x 32 halves (4 uint4/row)
        {
            int j = tid << 1;                    // 2 uint4 groups per thread per tile
#pragma unroll
            for (int s = 0; s < 2; s++) {
                int jj = j + s;                  // 0..511
                int r = jj >> 2, q = jj & 3;
                const uint4* sa_h = (const uint4*)(g_ahi + (size_t)(tm + r) * HID + k0);
                const uint4* sa_l = (const uint4*)(g_alo + (size_t)(tm + r) * HID + k0);
                const uint4* sb_h = (const uint4*)(g_whi + (size_t)(tn + r) * HID + k0);
                const uint4* sb_l = (const uint4*)(g_wlo + (size_t)(tn + r) * HID + k0);
                *(uint4*)&As[0][r][q * 8] = sa_h[q];
                *(uint4*)&As[1][r][q * 8] = sa_l[q];
                *(uint4*)&Bs[0][r][q * 8] = sb_h[q];
                *(uint4*)&Bs[1][r][q * 8] = sb_l[q];
            }
        }
        __syncthreads();

#pragma unroll
        for (int ks = 0; ks < 2; ks++) {
            int kk = ks * 16 + 2 * tig;
            unsigned bh[4][2], bl[4][2];
#pragma unroll
            for (int ni = 0; ni < 4; ni++) {
                int rn = wn * 32 + ni * 8 + g;
                bh[ni][0] = *(const unsigned*)&Bs[0][rn][kk];
                bh[ni][1] = *(const unsigned*)&Bs[0][rn][kk + 8];
                bl[ni][0] = *(const unsigned*)&Bs[1][rn][kk];
                bl[ni][1] = *(const unsigned*)&Bs[1][rn][kk + 8];
            }
#pragma unroll
            for (int mi = 0; mi < 4; mi++) {
                int rm = wm * 64 + mi * 16 + g;
                unsigned ah[4], al[4];
                ah[0] = *(const unsigned*)&As[0][rm][kk];
                ah[1] = *(const unsigned*)&As[0][rm + 8][kk];
                ah[2] = *(const unsigned*)&As[0][rm][kk + 8];
                ah[3] = *(const unsigned*)&As[0][rm + 8][kk + 8];
                al[0] = *(const unsigned*)&As[1][rm][kk];
                al[1] = *(const unsigned*)&As[1][rm + 8][kk];
                al[2] = *(const unsigned*)&As[1][rm][kk + 8];
                al[3] = *(const unsigned*)&As[1][rm + 8][kk + 8];
#pragma unroll
                for (int ni = 0; ni < 4; ni++) {
                    MMA_OP(acc[mi][ni], ah, bh[ni]);
                    MMA_OP(acc[mi][ni], ah, bl[ni]);
                    MMA_OP(acc[mi][ni], al, bh[ni]);
                }
            }
        }
    }

    // epilogue: c0,c1 -> (row g, cols 2tig..+1); c2,c3 -> (row g+8)
#pragma unroll
    for (int mi = 0; mi < 4; mi++) {
#pragma unroll
        for (int ni = 0; ni < 4; ni++) {
            int row = tm + wm * 64 + mi * 16 + g;
            int col = tn + wn * 32 + ni * 8 + 2 * tig;
            float o0 = g_outde[col], o1 = g_outde[col + 1];
            float2 r0 = { acc[mi][ni][0] + o0, acc[mi][ni][1] + o1 };
            float2 r1 = { acc[mi][ni][2] + o0, acc[mi][ni][3] + o1 };
            *(float2*)(out + (size_t)row * VOCAB + col) = r0;
            *(float2*)(out + (size_t)(row + 8) * VOCAB + col) = r1;
        }
    }
}

// ---------------- entry ------------------------------------------------------
extern "C" void kernel_launch(void* const* d_in, const int* in_sizes, int n_in,
                              void* d_out, int out_size) {
    const float* z      = (const float*)d_in[0];
    const float* cond   = (const float*)d_in[1];
    // d_in[2] = inputs (unused: word_dropout=1.0), d_in[3] = temperature (unused)
    const float* embedW = (const float*)d_in[4];
    const float* W_ih   = (const float*)d_in[5];
    const float* W_hh   = (const float*)d_in[6];
    const float* b_ih   = (const float*)d_in[7];
    const float* b_hh   = (const float*)d_in[8];
    const float* i2h_W  = (const float*)d_in[9];
    const float* i2h_b  = (const float*)d_in[10];
    const float* c2h_W  = (const float*)d_in[11];
    const float* c2h_b  = (const float*)d_in[12];
    const float* out_W  = (const float*)d_in[13];
    const float* out_b  = (const float*)d_in[14];
    float* out = (float*)d_out;

    prep_kernel<<<1, 256>>>(z, cond, i2h_W, i2h_b, c2h_W, c2h_b);
    gi_kernel<<<96, 256>>>(embedW, W_ih, b_ih, b_hh);
    outde_kernel<<<(VOCAB + 255) / 256, 256>>>(out_W, out_b);
    wconv_kernel<<<(VOCAB * (HID / 8) + 255) / 256, 256>>>(out_W);
    scan_kernel<<<SCAN_CTAS, 256>>>(W_hh, b_hh);
    aconv_kernel<<<(NSTEPS * (HID / 8) + 255) / 256, 256>>>();
    mma_gemm_kernel<<<dim3(VOCAB / 128, NSTEPS / 128), 256>>>(out);
}